// round 4
// baseline (speedup 1.0000x reference)
#include <cuda_runtime.h>

#define BATCHES 8
#define N_PER 8192
#define M_PER 2048
#define C_FEAT 32
#define K 32
#define NCH (3 + C_FEAT)              // 35
#define THREADS 640
#define WARPS (THREADS / 32)          // 20
#define CHUNKS 18                     // 18*8 = 144 CTAs = one wave at 1 CTA/SM
#define Q_PER_CHUNK 114               // 18*114 = 2052 >= 2048
#define M_TOT (BATCHES * M_PER)              // 16384
#define FEAT_ELEMS ((size_t)M_TOT * NCH * K) // 18350080
#define TP 33                                // tile pitch (floats), conflict-free

// smem layout (floats):
//  sxy   [0 .. 16384)          float2[8192]
//  sz    [16384 .. 24576)      float [8192]
//  ws    [24576 .. 25216)      int   [20*32]
//  tiles [25216 .. 46336)      float [20][32*TP]
//  qctr  [46336]
#define OFF_SZ    16384
#define OFF_WS    24576
#define OFF_TILE  25216
#define OFF_QCTR  46336
#define SMEM_BYTES ((OFF_QCTR + 4) * 4)

__global__ __launch_bounds__(THREADS, 1)
void sqag_kernel(const float* __restrict__ xyz,
                 const float* __restrict__ new_xyz,
                 const float* __restrict__ features,
                 float* __restrict__ out)
{
    extern __shared__ float smem[];
    float2* sxy   = (float2*)smem;
    float*  sz    = smem + OFF_SZ;
    int*    slots = (int*)(smem + OFF_WS);
    int*    qctr  = (int*)(smem + OFF_QCTR);

    const int batch = blockIdx.y;
    const int bbase = batch * N_PER;
    const float* bx = xyz + (size_t)bbase * 3;

    if (threadIdx.x == 0) *qctr = 0;

    // Stage this batch's xyz into SMEM (float2 xy + float z).
    for (int p = threadIdx.x; p < N_PER; p += THREADS) {
        const float* src = bx + 3 * p;
        sxy[p] = make_float2(src[0], src[1]);
        sz[p]  = src[2];
    }
    __syncthreads();

    const int wid  = threadIdx.x >> 5;
    const int lane = threadIdx.x & 31;
    int*   ws   = slots + wid * K;
    float* tile = smem + OFF_TILE + wid * (32 * TP);
    // JAX compares d2 < f32(0.04) = 0.039999999105930328f (NOT 0.2f*0.2f)
    const float R2 = (float)(0.2 * 0.2);
    const unsigned lanemask_lt = (1u << lane) - 1u;
    const int j4 = lane >> 3;   // 0..3  (row within gather round)
    const int cc = lane & 7;    // 0..7  (float4 chunk within row)

    const int q_start = blockIdx.x * Q_PER_CHUNK;
    const int nq = min(Q_PER_CHUNK, M_PER - q_start);

    for (;;) {
        int qt;
        if (lane == 0) qt = atomicAdd(qctr, 1);
        qt = __shfl_sync(0xffffffffu, qt, 0);
        if (qt >= nq) break;

        const int m = batch * M_PER + q_start + qt;
        const float* qp = new_xyz + (size_t)m * 3;
        const float qx = qp[0], qy = qp[1], qz = qp[2];

        // ---- scan: 256 candidates per exit check, xy prescreen, z on demand
        int cnt = 0;  // warp-uniform
        for (int j0 = 0; j0 < N_PER && cnt < K; j0 += 256) {
            float2 v[8];
            #pragma unroll
            for (int t = 0; t < 8; t++) v[t] = sxy[j0 + t * 32 + lane];
            #pragma unroll
            for (int t = 0; t < 8; t++) {
                const float dx = v[t].x - qx;
                const float dy = v[t].y - qy;
                const float sxy2 = __fadd_rn(__fmul_rn(dx, dx),
                                             __fmul_rn(dy, dy));
                bool inb = false;
                if (sxy2 < R2) {
                    const float dz = sz[j0 + t * 32 + lane] - qz;
                    const float d2 = __fadd_rn(sxy2, __fmul_rn(dz, dz));
                    inb = d2 < R2;
                }
                const unsigned mask = __ballot_sync(0xffffffffu, inb);
                if (inb) {
                    const int pos = cnt + __popc(mask & lanemask_lt);
                    if (pos < K) ws[pos] = j0 + t * 32 + lane;
                }
                cnt += __popc(mask);
            }
        }
        __syncwarp();

        const bool empty = (cnt == 0);
        const int c = cnt < K ? cnt : K;
        const float sc = empty ? 0.0f : 1.0f;

        // ---- coalesced feature gather -> per-warp smem tile (transpose)
        #pragma unroll
        for (int r = 0; r < 8; r++) {
            const int s = 4 * r + j4;
            const int sel = (s < c) ? s : 0;
            const int is = empty ? 0 : ws[sel];
            const float4 v = __ldg((const float4*)(features +
                                   (size_t)(bbase + is) * C_FEAT) + cc);
            float* dst = tile + s * TP + 4 * cc;
            dst[0] = v.x * sc; dst[1] = v.y * sc;
            dst[2] = v.z * sc; dst[3] = v.w * sc;
        }

        // ---- xyz channels (lane = k)
        int i = 0;
        if (!empty) i = (lane < c) ? ws[lane] : ws[0];
        const float2 pxy = sxy[i];
        const float  pz  = sz[i];
        const size_t ob = (size_t)m * (NCH * K);
        out[ob + 0 * K + lane] = (pxy.x - qx) * sc;
        out[ob + 1 * K + lane] = (pxy.y - qy) * sc;
        out[ob + 2 * K + lane] = (pz    - qz) * sc;

        __syncwarp();

        // ---- feature channels: read tile column (lane = k), coalesced stores
        #pragma unroll
        for (int t = 0; t < 8; t++) {
            const float* src = tile + lane * TP + 4 * t;
            out[ob + (size_t)(3 + 4 * t + 0) * K + lane] = src[0];
            out[ob + (size_t)(3 + 4 * t + 1) * K + lane] = src[1];
            out[ob + (size_t)(3 + 4 * t + 2) * K + lane] = src[2];
            out[ob + (size_t)(3 + 4 * t + 3) * K + lane] = src[3];
        }

        // Output dtype is float32: idx stored as float (0..8191 exact).
        out[FEAT_ELEMS + (size_t)m * K + lane] = empty ? 0.0f : (float)i;
        __syncwarp();
    }
}

extern "C" void kernel_launch(void* const* d_in, const int* in_sizes, int n_in,
                              void* d_out, int out_size)
{
    const float* xyz      = (const float*)d_in[0];
    // d_in[1]: xyz_batch_cnt (constant N_PER, unused)
    const float* new_xyz  = (const float*)d_in[2];
    // d_in[3]: new_xyz_batch_cnt (constant M_PER, unused)
    const float* features = (const float*)d_in[4];

    cudaFuncSetAttribute(sqag_kernel,
                         cudaFuncAttributeMaxDynamicSharedMemorySize, SMEM_BYTES);

    dim3 grid(CHUNKS, BATCHES);
    sqag_kernel<<<grid, THREADS, SMEM_BYTES>>>(xyz, new_xyz, features, (float*)d_out);
}

// round 5
// speedup vs baseline: 1.3536x; 1.3536x over previous
#include <cuda_runtime.h>

#define BATCHES 8
#define N_PER 8192
#define M_PER 2048
#define C_FEAT 32
#define K 32
#define NCH (3 + C_FEAT)              // 35
#define THREADS 960
#define WARPS (THREADS / 32)          // 30
#define CHUNKS 18                     // 18*8 = 144 CTAs, 1 per SM
#define Q_PER_CHUNK 114               // 17*114 + 110 = 2048
#define M_TOT (BATCHES * M_PER)              // 16384
#define FEAT_ELEMS ((size_t)M_TOT * NCH * K) // 18350080

// smem word layout:
//  sxy   [0, 16384)                      float2[8192]
//  sz    [16384, 24576)                  float[8192]
//  tiles [24576, 24576 + WARPS*1024)     32x32 floats per warp, XOR-swizzled
//  slots [.., +WARPS*32)
//  qctr  [last]
#define OFF_SZ    16384
#define OFF_TILE  24576
#define OFF_WS    (OFF_TILE + WARPS * 1024)        // 55296
#define OFF_QCTR  (OFF_WS + WARPS * 32)            // 56256
#define SMEM_BYTES ((OFF_QCTR + 4) * 4)            // ~225KB

__global__ __launch_bounds__(THREADS, 1)
void sqag_kernel(const float* __restrict__ xyz,
                 const float* __restrict__ new_xyz,
                 const float* __restrict__ features,
                 float* __restrict__ out)
{
    extern __shared__ float smem[];
    float2* sxy   = (float2*)smem;
    float*  sz    = smem + OFF_SZ;
    int*    slots = (int*)(smem + OFF_WS);
    int*    qctr  = (int*)(smem + OFF_QCTR);

    const int batch = blockIdx.y;
    const int bbase = batch * N_PER;
    const float* bx = xyz + (size_t)bbase * 3;

    if (threadIdx.x == 0) *qctr = 0;

    // Stage this batch's xyz into SMEM (float2 xy + float z).
    for (int p = threadIdx.x; p < N_PER; p += THREADS) {
        const float* src = bx + 3 * p;
        sxy[p] = make_float2(src[0], src[1]);
        sz[p]  = src[2];
    }
    __syncthreads();

    const int wid  = threadIdx.x >> 5;
    const int lane = threadIdx.x & 31;
    int*   ws   = slots + wid * K;
    float* tile = smem + OFF_TILE + wid * 1024;
    // JAX compares d2 < f32(0.04) = 0.039999999105930328f (NOT 0.2f*0.2f)
    const float R2 = (float)(0.2 * 0.2);
    const unsigned lanemask_lt = (1u << lane) - 1u;
    const int j4 = lane >> 3;   // 0..3 (row-in-round for gather)
    const int cc = lane & 7;    // 0..7 (float4 chunk within feature row)

    const int q_start = blockIdx.x * Q_PER_CHUNK;
    const int nq = min(Q_PER_CHUNK, M_PER - q_start);

    for (;;) {
        int qt;
        if (lane == 0) qt = atomicAdd(qctr, 1);
        qt = __shfl_sync(0xffffffffu, qt, 0);
        if (qt >= nq) break;

        const int m = batch * M_PER + q_start + qt;
        const float* qp = new_xyz + (size_t)m * 3;
        const float qx = qp[0], qy = qp[1], qz = qp[2];

        // ---- pipelined scan: 64 candidates per exit check, prefetch depth 64
        int cnt = 0;  // warp-uniform
        float2 a_xy = sxy[lane],      b_xy = sxy[32 + lane];
        float  a_z  = sz[lane],       b_z  = sz[32 + lane];
        for (int j0 = 0; j0 < N_PER && cnt < K; j0 += 64) {
            const int jn = j0 + 64;
            float2 c_xy, d_xy; float c_z, d_z;
            if (jn < N_PER) {
                c_xy = sxy[jn + lane]; d_xy = sxy[jn + 32 + lane];
                c_z  = sz[jn + lane];  d_z  = sz[jn + 32 + lane];
            }
            {
                const float dx = a_xy.x - qx, dy = a_xy.y - qy, dz = a_z - qz;
                const float d2 = __fadd_rn(__fadd_rn(__fmul_rn(dx, dx),
                                                     __fmul_rn(dy, dy)),
                                           __fmul_rn(dz, dz));
                const bool inb = d2 < R2;
                const unsigned mask = __ballot_sync(0xffffffffu, inb);
                if (inb) {
                    const int pos = cnt + __popc(mask & lanemask_lt);
                    if (pos < K) ws[pos] = j0 + lane;
                }
                cnt += __popc(mask);
            }
            {
                const float dx = b_xy.x - qx, dy = b_xy.y - qy, dz = b_z - qz;
                const float d2 = __fadd_rn(__fadd_rn(__fmul_rn(dx, dx),
                                                     __fmul_rn(dy, dy)),
                                           __fmul_rn(dz, dz));
                const bool inb = d2 < R2;
                const unsigned mask = __ballot_sync(0xffffffffu, inb);
                if (inb) {
                    const int pos = cnt + __popc(mask & lanemask_lt);
                    if (pos < K) ws[pos] = j0 + 32 + lane;
                }
                cnt += __popc(mask);
            }
            a_xy = c_xy; b_xy = d_xy; a_z = c_z; b_z = d_z;
        }
        __syncwarp();

        const bool empty = (cnt == 0);
        const int c = cnt < K ? cnt : K;
        const float sc = empty ? 0.0f : 1.0f;

        // lane s's neighbor index (with reference padding semantics)
        int i = 0;
        if (!empty) i = (lane < c) ? ws[lane] : ws[0];

        // ---- coalesced feature gather -> XOR-swizzled 4KB warp tile
        #pragma unroll
        for (int r = 0; r < 8; r++) {
            const int s  = 4 * r + j4;
            const int is = __shfl_sync(0xffffffffu, i, s);
            const float4 v = __ldg((const float4*)(features +
                                   (size_t)(bbase + is) * C_FEAT) + cc);
            float* dst = tile + s * 32 + ((4 * cc) ^ (4 * (s & 7)));
            dst[0] = v.x * sc; dst[1] = v.y * sc;
            dst[2] = v.z * sc; dst[3] = v.w * sc;
        }

        // ---- xyz channels (lane = k)
        const float2 pxy = sxy[i];
        const float  pz  = sz[i];
        const size_t ob = (size_t)m * (NCH * K);
        out[ob + 0 * K + lane] = (pxy.x - qx) * sc;
        out[ob + 1 * K + lane] = (pxy.y - qy) * sc;
        out[ob + 2 * K + lane] = (pz    - qz) * sc;

        __syncwarp();

        // ---- feature channels: lane k reads its tile row, coalesced stores
        #pragma unroll
        for (int t = 0; t < 8; t++) {
            const float* src = tile + lane * 32 + ((4 * t) ^ (4 * (lane & 7)));
            out[ob + (size_t)(3 + 4 * t + 0) * K + lane] = src[0];
            out[ob + (size_t)(3 + 4 * t + 1) * K + lane] = src[1];
            out[ob + (size_t)(3 + 4 * t + 2) * K + lane] = src[2];
            out[ob + (size_t)(3 + 4 * t + 3) * K + lane] = src[3];
        }

        // Output dtype is float32: idx stored as float (0..8191 exact).
        out[FEAT_ELEMS + (size_t)m * K + lane] = empty ? 0.0f : (float)i;
        __syncwarp();
    }
}

extern "C" void kernel_launch(void* const* d_in, const int* in_sizes, int n_in,
                              void* d_out, int out_size)
{
    const float* xyz      = (const float*)d_in[0];
    // d_in[1]: xyz_batch_cnt (constant N_PER, unused)
    const float* new_xyz  = (const float*)d_in[2];
    // d_in[3]: new_xyz_batch_cnt (constant M_PER, unused)
    const float* features = (const float*)d_in[4];

    cudaFuncSetAttribute(sqag_kernel,
                         cudaFuncAttributeMaxDynamicSharedMemorySize, SMEM_BYTES);

    dim3 grid(CHUNKS, BATCHES);
    sqag_kernel<<<grid, THREADS, SMEM_BYTES>>>(xyz, new_xyz, features, (float*)d_out);
}

// round 6
// speedup vs baseline: 1.4059x; 1.0387x over previous
#include <cuda_runtime.h>

#define BATCHES 8
#define N_PER 8192
#define M_PER 2048
#define C_FEAT 32
#define K 32
#define NCH (3 + C_FEAT)              // 35
#define THREADS 960
#define WARPS (THREADS / 32)          // 30
#define CHUNKS 18                     // 18*8 = 144 CTAs, 1 per SM
#define Q_PER_CHUNK 114               // covers 2048
#define M_TOT (BATCHES * M_PER)              // 16384
#define FEAT_ELEMS ((size_t)M_TOT * NCH * K) // 18350080

// smem word layout:
//  sxy   [0, 16384)                      float2[8192]
//  sz    [16384, 24576)                  float[8192]
//  tiles [24576, 24576 + WARPS*1024)     32x32 floats per warp, XOR-swizzled
//  slots [.., +WARPS*32)
//  qctr  [last]
#define OFF_SZ    16384
#define OFF_TILE  24576
#define OFF_WS    (OFF_TILE + WARPS * 1024)        // 55296
#define OFF_QCTR  (OFF_WS + WARPS * 32)            // 56256
#define SMEM_BYTES ((OFF_QCTR + 4) * 4)            // ~225KB

__global__ __launch_bounds__(THREADS, 1)
void sqag_kernel(const float* __restrict__ xyz,
                 const float* __restrict__ new_xyz,
                 const float* __restrict__ features,
                 float* __restrict__ out)
{
    extern __shared__ float smem[];
    float2* sxy   = (float2*)smem;
    float*  sz    = smem + OFF_SZ;
    int*    slots = (int*)(smem + OFF_WS);
    int*    qctr  = (int*)(smem + OFF_QCTR);

    const int batch = blockIdx.y;
    const int bbase = batch * N_PER;
    const float* bx = xyz + (size_t)bbase * 3;

    if (threadIdx.x == 0) *qctr = 0;

    // Stage this batch's xyz into SMEM (float2 xy + float z).
    for (int p = threadIdx.x; p < N_PER; p += THREADS) {
        const float* src = bx + 3 * p;
        sxy[p] = make_float2(src[0], src[1]);
        sz[p]  = src[2];
    }
    __syncthreads();

    const int wid  = threadIdx.x >> 5;
    const int lane = threadIdx.x & 31;
    int*   ws   = slots + wid * K;
    float* tile = smem + OFF_TILE + wid * 1024;
    // JAX compares d2 < f32(0.04) = 0.039999999105930328f (NOT 0.2f*0.2f)
    const float R2 = (float)(0.2 * 0.2);
    const unsigned lanemask_lt = (1u << lane) - 1u;
    const unsigned lanebit = 1u << lane;
    const int j4 = lane >> 3;   // 0..3 (row-in-round for gather)
    const int cc = lane & 7;    // 0..7 (float4 chunk within feature row)

    const int q_start = blockIdx.x * Q_PER_CHUNK;
    const int nq = min(Q_PER_CHUNK, M_PER - q_start);

    for (;;) {
        int qt;
        if (lane == 0) qt = atomicAdd(qctr, 1);
        qt = __shfl_sync(0xffffffffu, qt, 0);
        if (qt >= nq) break;

        const int m = batch * M_PER + q_start + qt;
        const float* qp = new_xyz + (size_t)m * 3;
        const float qx = qp[0], qy = qp[1], qz = qp[2];

        // ---- scan: 128 candidates per exit check, 4 independent ballot chains
        int cnt = 0;  // warp-uniform
        for (int j0 = 0; j0 < N_PER && cnt < K; j0 += 128) {
            float2 xy[4]; float zz[4];
            #pragma unroll
            for (int t = 0; t < 4; t++) {
                xy[t] = sxy[j0 + t * 32 + lane];
                zz[t] = sz[j0 + t * 32 + lane];
            }
            unsigned msk[4];
            #pragma unroll
            for (int t = 0; t < 4; t++) {
                const float dx = xy[t].x - qx;
                const float dy = xy[t].y - qy;
                const float dz = zz[t]   - qz;
                const float d2 = __fadd_rn(__fadd_rn(__fmul_rn(dx, dx),
                                                     __fmul_rn(dy, dy)),
                                           __fmul_rn(dz, dz));
                msk[t] = __ballot_sync(0xffffffffu, d2 < R2);
            }
            int base = cnt;
            #pragma unroll
            for (int t = 0; t < 4; t++) {
                if (msk[t] & lanebit) {
                    const int pos = base + __popc(msk[t] & lanemask_lt);
                    if (pos < K) ws[pos] = j0 + t * 32 + lane;
                }
                base += __popc(msk[t]);
            }
            cnt = base;
        }
        __syncwarp();

        const bool empty = (cnt == 0);
        const int c = cnt < K ? cnt : K;
        const float sc = empty ? 0.0f : 1.0f;

        // lane s's neighbor index (with reference padding semantics)
        int i = 0;
        if (!empty) i = (lane < c) ? ws[lane] : ws[0];

        // ---- coalesced feature gather -> XOR-swizzled 4KB warp tile (STS.128)
        #pragma unroll
        for (int r = 0; r < 8; r++) {
            const int s  = 4 * r + j4;
            const int is = __shfl_sync(0xffffffffu, i, s);
            float4 v = __ldg((const float4*)(features +
                             (size_t)(bbase + is) * C_FEAT) + cc);
            v.x *= sc; v.y *= sc; v.z *= sc; v.w *= sc;
            *(float4*)(tile + s * 32 + ((4 * cc) ^ (4 * (s & 7)))) = v;
        }

        // ---- xyz channels (lane = k)
        const float2 pxy = sxy[i];
        const float  pz  = sz[i];
        const size_t ob = (size_t)m * (NCH * K);
        out[ob + 0 * K + lane] = (pxy.x - qx) * sc;
        out[ob + 1 * K + lane] = (pxy.y - qy) * sc;
        out[ob + 2 * K + lane] = (pz    - qz) * sc;

        __syncwarp();

        // ---- feature channels: lane k reads its tile row (LDS.128), coalesced STG
        #pragma unroll
        for (int t = 0; t < 8; t++) {
            const float4 v = *(const float4*)(tile + lane * 32 +
                                              ((4 * t) ^ (4 * (lane & 7))));
            out[ob + (size_t)(3 + 4 * t + 0) * K + lane] = v.x;
            out[ob + (size_t)(3 + 4 * t + 1) * K + lane] = v.y;
            out[ob + (size_t)(3 + 4 * t + 2) * K + lane] = v.z;
            out[ob + (size_t)(3 + 4 * t + 3) * K + lane] = v.w;
        }

        // Output dtype is float32: idx stored as float (0..8191 exact).
        out[FEAT_ELEMS + (size_t)m * K + lane] = empty ? 0.0f : (float)i;
        __syncwarp();
    }
}

extern "C" void kernel_launch(void* const* d_in, const int* in_sizes, int n_in,
                              void* d_out, int out_size)
{
    const float* xyz      = (const float*)d_in[0];
    // d_in[1]: xyz_batch_cnt (constant N_PER, unused)
    const float* new_xyz  = (const float*)d_in[2];
    // d_in[3]: new_xyz_batch_cnt (constant M_PER, unused)
    const float* features = (const float*)d_in[4];

    cudaFuncSetAttribute(sqag_kernel,
                         cudaFuncAttributeMaxDynamicSharedMemorySize, SMEM_BYTES);

    dim3 grid(CHUNKS, BATCHES);
    sqag_kernel<<<grid, THREADS, SMEM_BYTES>>>(xyz, new_xyz, features, (float*)d_out);
}